// round 1
// baseline (speedup 1.0000x reference)
#include <cuda_runtime.h>

#define BATCH   65536
#define D0      768
#define D1      512
#define D2      256
#define D3      128
#define NCODES  256
#define NLEVELS 4
#define BETA_F  0.25f
#define QBLOCKS 256

// ---------------- scratch (no cudaMalloc allowed) ----------------
__device__ float g_h1[(size_t)BATCH * D1];   // 128 MB: enc h1 / dec h2
__device__ float g_h2[(size_t)BATCH * D2];   //  64 MB: enc h2 / dec h1
__device__ float g_z [(size_t)BATCH * D3];   //  32 MB: encoder output z
__device__ float g_res[(size_t)BATCH * D3];  //  32 MB: running residual
__device__ float g_xq [(size_t)BATCH * D3];  //  32 MB: accumulated x_q
__device__ float g_loss_part[NLEVELS * QBLOCKS];

// ---------------- tiled fp32 GEMM: C = act(A@W + bias) ----------------
// BM=128, BN=64, BK=16, TM=8, TN=4, 256 threads.
template <bool RELU>
__global__ __launch_bounds__(256) void sgemm_bias(
    const float* __restrict__ A, const float* __restrict__ W,
    const float* __restrict__ bias, float* __restrict__ C,
    int M, int N, int K)
{
    constexpr int BM = 128, BN = 64, BK = 16, TM = 8, TN = 4;
    __shared__ __align__(16) float As[BK][BM];
    __shared__ __align__(16) float Bs[BK][BN];

    const int tid = threadIdx.x;
    const int tx  = tid & 15;   // col group (16 groups * TN=4 -> 64)
    const int ty  = tid >> 4;   // row group (16 groups * TM=8 -> 128)
    const int rowBase = blockIdx.y * BM;
    const int colBase = blockIdx.x * BN;

    float acc[TM][TN];
#pragma unroll
    for (int i = 0; i < TM; i++)
#pragma unroll
        for (int j = 0; j < TN; j++) acc[i][j] = 0.0f;

    for (int k0 = 0; k0 < K; k0 += BK) {
        // A tile: 128x16 = 512 float4, 2 per thread, stored transposed
#pragma unroll
        for (int t = 0; t < 2; t++) {
            int f  = tid + t * 256;
            int ar = f >> 2;        // 0..127
            int aq = f & 3;         // 0..3 (float4 within row)
            float4 v = *reinterpret_cast<const float4*>(
                &A[(size_t)(rowBase + ar) * K + k0 + aq * 4]);
            As[aq * 4 + 0][ar] = v.x;
            As[aq * 4 + 1][ar] = v.y;
            As[aq * 4 + 2][ar] = v.z;
            As[aq * 4 + 3][ar] = v.w;
        }
        // B tile: 16x64 = 256 float4, 1 per thread
        {
            int br = tid >> 4;  // k row 0..15
            int bc = tid & 15;  // col group
            float4 v = *reinterpret_cast<const float4*>(
                &W[(size_t)(k0 + br) * N + colBase + bc * 4]);
            *reinterpret_cast<float4*>(&Bs[br][bc * 4]) = v;
        }
        __syncthreads();

#pragma unroll
        for (int kk = 0; kk < BK; kk++) {
            float4 a0 = *reinterpret_cast<const float4*>(&As[kk][ty * TM]);
            float4 a1 = *reinterpret_cast<const float4*>(&As[kk][ty * TM + 4]);
            float4 b  = *reinterpret_cast<const float4*>(&Bs[kk][tx * TN]);
            float a[TM] = {a0.x, a0.y, a0.z, a0.w, a1.x, a1.y, a1.z, a1.w};
#pragma unroll
            for (int i = 0; i < TM; i++) {
                acc[i][0] += a[i] * b.x;
                acc[i][1] += a[i] * b.y;
                acc[i][2] += a[i] * b.z;
                acc[i][3] += a[i] * b.w;
            }
        }
        __syncthreads();
    }

    float4 bv = *reinterpret_cast<const float4*>(&bias[colBase + tx * TN]);
#pragma unroll
    for (int i = 0; i < TM; i++) {
        int r = rowBase + ty * TM + i;
        float4 o;
        o.x = acc[i][0] + bv.x;
        o.y = acc[i][1] + bv.y;
        o.z = acc[i][2] + bv.z;
        o.w = acc[i][3] + bv.w;
        if (RELU) {
            o.x = fmaxf(o.x, 0.0f); o.y = fmaxf(o.y, 0.0f);
            o.z = fmaxf(o.z, 0.0f); o.w = fmaxf(o.w, 0.0f);
        }
        *reinterpret_cast<float4*>(&C[(size_t)r * N + colBase + tx * TN]) = o;
    }
}

// ---------------- one residual-quantization level ----------------
// One thread = one row. Residual (128 floats) lives in registers.
// Codebook level streamed through smem in 4 chunks of 64 codes (32 KB).
__global__ __launch_bounds__(256) void quant_level(
    const float* __restrict__ resIn, float* __restrict__ resOut,
    float* __restrict__ xq, const float* __restrict__ codebooks,
    int level, int initxq, float* __restrict__ partials)
{
    const float* C = codebooks + (size_t)level * NCODES * D3;
    __shared__ __align__(16) float sC[64 * D3];  // 32 KB chunk
    __shared__ float snorm[64];
    __shared__ float sred[256];

    const int tid = threadIdx.x;
    const size_t row = (size_t)blockIdx.x * 256 + tid;

    float4 r[32];
    const float4* rp = reinterpret_cast<const float4*>(resIn + row * D3);
#pragma unroll
    for (int i = 0; i < 32; i++) r[i] = rp[i];

    float best = 3.4e38f;
    int bi = 0;

    for (int ch = 0; ch < 4; ch++) {
        __syncthreads();
        const float4* src = reinterpret_cast<const float4*>(C + (size_t)ch * 64 * D3);
        float4* dst = reinterpret_cast<float4*>(sC);
#pragma unroll
        for (int i = 0; i < 8; i++) dst[tid + i * 256] = src[tid + i * 256];
        __syncthreads();
        if (tid < 64) {
            const float4* cp = reinterpret_cast<const float4*>(sC + tid * D3);
            float s = 0.0f;
#pragma unroll
            for (int i = 0; i < 32; i++) {
                float4 v = cp[i];
                s += v.x * v.x + v.y * v.y + v.z * v.z + v.w * v.w;
            }
            snorm[tid] = s;
        }
        __syncthreads();

        for (int c = 0; c < 64; c++) {
            const float4* cp = reinterpret_cast<const float4*>(sC + c * D3);
            float ax = 0.f, ay = 0.f, az = 0.f, aw = 0.f;
#pragma unroll
            for (int i = 0; i < 32; i++) {
                float4 v = cp[i];
                ax += r[i].x * v.x;
                ay += r[i].y * v.y;
                az += r[i].z * v.z;
                aw += r[i].w * v.w;
            }
            float dot = (ax + ay) + (az + aw);
            float score = snorm[c] - 2.0f * dot;   // ||c||^2 - 2 r.c
            if (score < best) { best = score; bi = ch * 64 + c; }
        }
    }

    // apply chosen code
    const float4* qp = reinterpret_cast<const float4*>(C + (size_t)bi * D3);
    float4* rop = reinterpret_cast<float4*>(resOut + row * D3);
    float4* xp  = reinterpret_cast<float4*>(xq + row * D3);
    float ls = 0.0f;
#pragma unroll
    for (int i = 0; i < 32; i++) {
        float4 q = qp[i];
        float dx = q.x - r[i].x, dy = q.y - r[i].y;
        float dz = q.z - r[i].z, dw = q.w - r[i].w;
        ls += dx * dx + dy * dy + dz * dz + dw * dw;
        float4 nr = make_float4(r[i].x - q.x, r[i].y - q.y,
                                r[i].z - q.z, r[i].w - q.w);
        rop[i] = nr;
        if (initxq) {
            xp[i] = q;
        } else {
            float4 o = xp[i];
            xp[i] = make_float4(o.x + q.x, o.y + q.y, o.z + q.z, o.w + q.w);
        }
    }

    // deterministic block reduction of squared error
    sred[tid] = ls;
    __syncthreads();
#pragma unroll
    for (int s = 128; s > 0; s >>= 1) {
        if (tid < s) sred[tid] += sred[tid + s];
        __syncthreads();
    }
    if (tid == 0) partials[level * QBLOCKS + blockIdx.x] = sred[0];
}

// ---------------- deterministic loss finalize ----------------
__global__ void finalize_loss(const float* __restrict__ partials,
                              float* __restrict__ out)
{
    if (threadIdx.x == 0 && blockIdx.x == 0) {
        float tot = 0.0f;
        for (int i = 0; i < NLEVELS * QBLOCKS; i++) tot += partials[i];
        // per-level loss = (1+beta) * sum_l / (B*D3); rq = mean over levels
        float rq = (1.0f + BETA_F) * tot /
                   ((float)NLEVELS * (float)BATCH * (float)D3);
        *out = rq;
    }
}

// ---------------- launch ----------------
extern "C" void kernel_launch(void* const* d_in, const int* in_sizes, int n_in,
                              void* d_out, int out_size)
{
    (void)in_sizes; (void)n_in;
    const float* x   = (const float*)d_in[0];
    const float* ew0 = (const float*)d_in[1];
    const float* eb0 = (const float*)d_in[2];
    const float* ew1 = (const float*)d_in[3];
    const float* eb1 = (const float*)d_in[4];
    const float* ew2 = (const float*)d_in[5];
    const float* eb2 = (const float*)d_in[6];
    const float* dw0 = (const float*)d_in[7];
    const float* db0 = (const float*)d_in[8];
    const float* dw1 = (const float*)d_in[9];
    const float* db1 = (const float*)d_in[10];
    const float* dw2 = (const float*)d_in[11];
    const float* db2 = (const float*)d_in[12];
    const float* cb  = (const float*)d_in[13];
    float* out = (float*)d_out;

    float *h1, *h2, *z, *res, *xq, *lp;
    cudaGetSymbolAddress((void**)&h1,  g_h1);
    cudaGetSymbolAddress((void**)&h2,  g_h2);
    cudaGetSymbolAddress((void**)&z,   g_z);
    cudaGetSymbolAddress((void**)&res, g_res);
    cudaGetSymbolAddress((void**)&xq,  g_xq);
    cudaGetSymbolAddress((void**)&lp,  g_loss_part);

    const int MB = BATCH / 128;

    // encoder
    sgemm_bias<true ><<<dim3(D1 / 64, MB), 256>>>(x,  ew0, eb0, h1, BATCH, D1, D0);
    sgemm_bias<true ><<<dim3(D2 / 64, MB), 256>>>(h1, ew1, eb1, h2, BATCH, D2, D1);
    sgemm_bias<false><<<dim3(D3 / 64, MB), 256>>>(h2, ew2, eb2, z,  BATCH, D3, D2);

    // residual quantization (4 levels)
    quant_level<<<QBLOCKS, 256>>>(z,   res, xq, cb, 0, 1, lp);
    quant_level<<<QBLOCKS, 256>>>(res, res, xq, cb, 1, 0, lp);
    quant_level<<<QBLOCKS, 256>>>(res, res, xq, cb, 2, 0, lp);
    quant_level<<<QBLOCKS, 256>>>(res, res, xq, cb, 3, 0, lp);

    // decoder (y_q == x_q in forward value)
    sgemm_bias<true ><<<dim3(D2 / 64, MB), 256>>>(xq, dw0, db0, h2,  BATCH, D2, D3);
    sgemm_bias<true ><<<dim3(D1 / 64, MB), 256>>>(h2, dw1, db1, h1,  BATCH, D1, D2);
    sgemm_bias<false><<<dim3(D0 / 64, MB), 256>>>(h1, dw2, db2, out, BATCH, D0, D1);

    // scalar rq_loss appended after y
    finalize_loss<<<1, 32>>>(lp, out + (size_t)out_size - 1);
}